// round 16
// baseline (speedup 1.0000x reference)
#include <cuda_runtime.h>
#include <math.h>

#define N_NODES 100000
#define N_EDGES 1600000
#define F_IN    128
#define E_DIM   16
#define HID     64
#define G_NUM   64
#define OUT_DIM 10
#define MAXDEG  64

// ---------------- scratch (device globals; no allocations allowed) ----------------
__device__ __align__(16) float g_xtrans[N_NODES * HID];   // 25.6 MB
__device__ __align__(16) float g_skip[N_NODES * HID];     // 25.6 MB
__device__ float  g_ax[N_NODES];
__device__ __align__(16) float g_acc[N_NODES * 128];      // [wx(64) | wh(64)] per node
__device__ float  g_den[N_NODES];
__device__ int    g_cnt_e[N_NODES];                       // edges per dst
__device__ __align__(16) int g_bucket[(size_t)N_NODES * MAXDEG];  // eid per dst slot (25.6 MB)
__device__ __align__(16) float g_wt[128 * 128];           // [k][c] c<64: W_lin, c>=64: W_skip
__device__ __align__(16) float2 g_we1t2[16 * 32];         // [k][lane] = (W_e1[2l][k], W_e1[2l+1][k])
__device__ __align__(16) float g_u[64];                   // W_e2^T . att
__device__ __align__(16) float g_hloop[64];               // relu(b_e1)
__device__ __align__(16) float g_be1_raw[64];             // raw b_e1
__device__ float  g_cscal[1];                             // b_e2 . att
__device__ float  g_aloop[1];                             // hloop.u + c
__device__ float  g_sums[G_NUM * HID];
__device__ float  g_cnt[G_NUM];
__device__ int    g_work;                                 // work-stealing cursor

// ---------------- f32x2 helpers ----------------------------------------------------
__device__ __forceinline__ unsigned long long pack2(float x, float y) {
    unsigned long long r;
    asm("mov.b64 %0, {%1, %2};" : "=l"(r) : "f"(x), "f"(y));
    return r;
}
__device__ __forceinline__ void unpack2(unsigned long long v, float& x, float& y) {
    asm("mov.b64 {%0, %1}, %2;" : "=f"(x), "=f"(y) : "l"(v));
}
__device__ __forceinline__ unsigned long long fma2(unsigned long long a, unsigned long long b,
                                                   unsigned long long c) {
    unsigned long long d;
    asm("fma.rn.f32x2 %0, %1, %2, %3;" : "=l"(d) : "l"(a), "l"(b), "l"(c));
    return d;
}
__device__ __forceinline__ unsigned long long add2(unsigned long long a, unsigned long long b) {
    unsigned long long d;
    asm("add.rn.f32x2 %0, %1, %2;" : "=l"(d) : "l"(a), "l"(b));
    return d;
}
__device__ __forceinline__ float getc(float4 v, int k) {
    return k == 0 ? v.x : (k == 1 ? v.y : (k == 2 ? v.z : v.w));
}

// ---------------- K_pre: weight prep + ALL zeroing (replaces memsets) --------------
__global__ void kpre(const float* __restrict__ Wlin, const float* __restrict__ Wskip,
                     const float* __restrict__ We1,  const float* __restrict__ be1,
                     const float* __restrict__ We2,  const float* __restrict__ be2,
                     const float* __restrict__ att) {
    int b = blockIdx.x, t = threadIdx.x;  // grid 104, 256 threads

    for (int i = b * 256 + t; i < N_NODES; i += 104 * 256) g_cnt_e[i] = 0;

    if (b == 1) {
        for (int i = t; i < G_NUM * HID; i += 256) g_sums[i] = 0.f;
        if (t < G_NUM) g_cnt[t] = 0.f;
        if (t == 0) g_work = 0;
    }
    if (b != 0) return;

    for (int i = t; i < 128 * 128; i += 256) {
        int k = i >> 7, c = i & 127;
        g_wt[i] = (c < 64) ? Wlin[c * 128 + k] : Wskip[(c - 64) * 128 + k];
    }
    for (int i = t; i < 16 * 32; i += 256) {
        int k = i >> 5, l = i & 31;
        g_we1t2[i] = make_float2(We1[(2 * l) * 16 + k], We1[(2 * l + 1) * 16 + k]);
    }
    if (t < 64) {
        float uu = 0.f;
        for (int d = 0; d < 64; d++) uu += We2[d * 64 + t] * att[d];
        g_u[t] = uu;
        g_hloop[t] = fmaxf(be1[t], 0.f);
        g_be1_raw[t] = be1[t];
    }
    __syncthreads();
    if (t == 0) {
        float cc = 0.f;
        for (int d = 0; d < 64; d++) cc += be2[d] * att[d];
        g_cscal[0] = cc;
        float al = cc;
        for (int h = 0; h < 64; h++) al += g_hloop[h] * g_u[h];
        g_aloop[0] = al;
    }
}

// ---------------- K_nb: fused node GEMM + edge bucketing (interleaved blocks) -----
__global__ __launch_bounds__(256) void k_nb(const float* __restrict__ x,
                                            const float* __restrict__ att,
                                            const int* __restrict__ ei) {
    __shared__ __align__(16) float xs[64 * 64];
    __shared__ __align__(16) float wsm[64 * 128];
    int b = blockIdx.x;
    int t = threadIdx.x, lane = t & 31, w = t >> 5;

    if (b % 5 != 0) {
        // ---- bucket path ----
        int bb = b - b / 5 - 1;
        int e = bb * 256 + t;
        if (e < N_EDGES) {
            int dst = __ldg(ei + N_EDGES + e);
            int pos = atomicAdd(&g_cnt_e[dst], 1);
            if (pos < MAXDEG) g_bucket[(size_t)dst * MAXDEG + pos] = e;
        }
        return;
    }

    // ---- node GEMM path ----
    int nodeBase = (b / 5) * 64;

    unsigned long long acc[8][2];
#pragma unroll
    for (int n = 0; n < 8; n++) { acc[n][0] = pack2(0.f, 0.f); acc[n][1] = pack2(0.f, 0.f); }

    for (int kb = 0; kb < 128; kb += 64) {
#pragma unroll
        for (int j = 0; j < 4; j++) {
            int i4 = t + j * 256;
            int nl = i4 >> 4, kk4 = i4 & 15;
            int node = nodeBase + nl;
            float4 v = make_float4(0.f, 0.f, 0.f, 0.f);
            if (node < N_NODES) v = __ldg((const float4*)x + node * 32 + (kb >> 2) + kk4);
            ((float4*)xs)[nl * 16 + kk4] = v;
        }
#pragma unroll
        for (int j = 0; j < 8; j++) {
            int i4 = t + j * 256;
            ((float4*)wsm)[i4] = ((const float4*)g_wt)[((kb + (i4 >> 5)) << 5) + (i4 & 31)];
        }
        __syncthreads();
        // quad-k inner loop: 4 weight vectors + float4 x broadcasts
#pragma unroll 4
        for (int k4 = 0; k4 < 16; k4++) {
            ulonglong2 wv0 = ((const ulonglong2*)wsm)[(4 * k4 + 0) * 32 + lane];
            ulonglong2 wv1 = ((const ulonglong2*)wsm)[(4 * k4 + 1) * 32 + lane];
            ulonglong2 wv2 = ((const ulonglong2*)wsm)[(4 * k4 + 2) * 32 + lane];
            ulonglong2 wv3 = ((const ulonglong2*)wsm)[(4 * k4 + 3) * 32 + lane];
#pragma unroll
            for (int n = 0; n < 8; n++) {
                float4 xq = ((const float4*)xs)[(w * 8 + n) * 16 + k4];
                acc[n][0] = fma2(pack2(xq.x, xq.x), wv0.x, acc[n][0]);
                acc[n][1] = fma2(pack2(xq.x, xq.x), wv0.y, acc[n][1]);
                acc[n][0] = fma2(pack2(xq.y, xq.y), wv1.x, acc[n][0]);
                acc[n][1] = fma2(pack2(xq.y, xq.y), wv1.y, acc[n][1]);
                acc[n][0] = fma2(pack2(xq.z, xq.z), wv2.x, acc[n][0]);
                acc[n][1] = fma2(pack2(xq.z, xq.z), wv2.y, acc[n][1]);
                acc[n][0] = fma2(pack2(xq.w, xq.w), wv3.x, acc[n][0]);
                acc[n][1] = fma2(pack2(xq.w, xq.w), wv3.y, acc[n][1]);
            }
        }
        __syncthreads();
    }

    float4 av = make_float4(0.f, 0.f, 0.f, 0.f);
    if (lane < 16) av = __ldg((const float4*)att + lane);
#pragma unroll
    for (int n = 0; n < 8; n++) {
        int node = nodeBase + w * 8 + n;
        float o0, o1, o2, o3;
        unpack2(acc[n][0], o0, o1);
        unpack2(acc[n][1], o2, o3);
        float part = o0 * av.x + o1 * av.y + o2 * av.z + o3 * av.w;
#pragma unroll
        for (int off = 16; off; off >>= 1) part += __shfl_xor_sync(0xffffffffu, part, off);
        if (node < N_NODES) {
            float4 v = make_float4(o0, o1, o2, o3);
            if (lane < 16) ((float4*)g_xtrans)[node * 16 + lane] = v;
            else           ((float4*)g_skip)[node * 16 + (lane - 16)] = v;
            if (lane == 0) g_ax[node] = part;
        }
    }
}

// ---------------- K_gather: work-stealing warps, 2-edge ILP, folded reduction -----
__global__ __launch_bounds__(256, 3) void k_gather(const int* __restrict__ ei,
                                                   const float* __restrict__ ea) {
    __shared__ __align__(16) float2 wsh[8 * 32];
    int t = threadIdx.x, lane = t & 31;
    int half = lane >> 4;
#pragma unroll
    for (int j = t; j < 256; j += 256) wsh[j] = g_we1t2[256 + j];
    __syncthreads();

    unsigned long long w2r[8];
#pragma unroll
    for (int k = 0; k < 8; k++) {
        float2 f = g_we1t2[k * 32 + lane];
        w2r[k] = pack2(f.x, f.y);
    }
    float bx = g_be1_raw[2 * lane], by = g_be1_raw[2 * lane + 1];
    float2 uu = ((const float2*)g_u)[lane];
    float cconst = g_cscal[0];

    while (true) {
        int base;
        if (lane == 0) base = atomicAdd(&g_work, 4);
        base = __shfl_sync(0xffffffffu, base, 0);
        if (base >= N_NODES) break;
        int lim = min(base + 4, N_NODES);

        for (int i = base; i < lim; i++) {
            int n = min(g_cnt_e[i], MAXDEG);
            const int* row = g_bucket + (size_t)i * MAXDEG;

            unsigned long long wx = pack2(0.f, 0.f), wh = pack2(0.f, 0.f);
            float sw = 0.f;

            if (n > 0) {
                int m = n - 1;
                int eA = __ldg(row);
                int eB = __ldg(row + min(1, m));
                int sA = __ldg(ei + eA);
                int sB = __ldg(ei + eB);

                for (int j = 0; j < n; j += 2) {
                    bool hasB = (j + 1 < n);
                    int ceA = eA, ceB = eB, csA = sA, csB = sB;

                    eA = __ldg(row + min(j + 2, m));
                    eB = __ldg(row + min(j + 3, m));
                    sA = __ldg(ei + eA);
                    sB = __ldg(ei + eB);

                    float axA = __ldg(&g_ax[csA]);
                    float axB = __ldg(&g_ax[csB]);
                    float2 xvA = __ldg((const float2*)g_xtrans + (size_t)csA * 32 + lane);
                    float2 xvB = __ldg((const float2*)g_xtrans + (size_t)csB * 32 + lane);

                    const float4* qA = (const float4*)ea + (size_t)ceA * 4;
                    const float4* qB = (const float4*)ea + (size_t)ceB * 4;

                    unsigned long long hA = pack2(bx, by), hB = pack2(bx, by);
                    {
                        float4 A0 = __ldg(qA), A1 = __ldg(qA + 1);
                        float4 B0 = __ldg(qB), B1 = __ldg(qB + 1);
#pragma unroll
                        for (int k = 0; k < 4; k++) {
                            float a = getc(A0, k), b = getc(B0, k);
                            hA = fma2(pack2(a, a), w2r[k], hA);
                            hB = fma2(pack2(b, b), w2r[k], hB);
                        }
#pragma unroll
                        for (int k = 0; k < 4; k++) {
                            float a = getc(A1, k), b = getc(B1, k);
                            hA = fma2(pack2(a, a), w2r[4 + k], hA);
                            hB = fma2(pack2(b, b), w2r[4 + k], hB);
                        }
                    }
                    {
                        float4 A0 = __ldg(qA + 2), A1 = __ldg(qA + 3);
                        float4 B0 = __ldg(qB + 2), B1 = __ldg(qB + 3);
#pragma unroll
                        for (int k = 0; k < 4; k++) {
                            float2 wk = wsh[k * 32 + lane];
                            unsigned long long wkp = pack2(wk.x, wk.y);
                            float a = getc(A0, k), b = getc(B0, k);
                            hA = fma2(pack2(a, a), wkp, hA);
                            hB = fma2(pack2(b, b), wkp, hB);
                        }
#pragma unroll
                        for (int k = 0; k < 4; k++) {
                            float2 wk = wsh[(4 + k) * 32 + lane];
                            unsigned long long wkp = pack2(wk.x, wk.y);
                            float a = getc(A1, k), b = getc(B1, k);
                            hA = fma2(pack2(a, a), wkp, hA);
                            hB = fma2(pack2(b, b), wkp, hB);
                        }
                    }

                    float hA0, hA1, hB0, hB1;
                    unpack2(hA, hA0, hA1);
                    unpack2(hB, hB0, hB1);
                    hA0 = fmaxf(hA0, 0.f); hA1 = fmaxf(hA1, 0.f);
                    hB0 = fmaxf(hB0, 0.f); hB1 = fmaxf(hB1, 0.f);

                    float pA = hA0 * uu.x + hA1 * uu.y;
                    float pB = hB0 * uu.x + hB1 * uu.y;
                    float zA = pA + __shfl_xor_sync(0xffffffffu, pA, 16);
                    float zB = pB + __shfl_xor_sync(0xffffffffu, pB, 16);
                    float z = half ? zB : zA;
#pragma unroll
                    for (int off = 8; off; off >>= 1) z += __shfl_xor_sync(0xffffffffu, z, off);

                    float al = (half ? axB : axA) + z + cconst;
                    al = al > 0.f ? al : 0.2f * al;
                    bool valid = (half == 0) || hasB;
                    float wgt = valid ? __expf(al) : 0.f;
                    float wgtO = __shfl_xor_sync(0xffffffffu, wgt, 16);
                    float wgtA = half ? wgtO : wgt;
                    float wgtB = half ? wgt : wgtO;

                    wx = fma2(pack2(wgtA, wgtA), pack2(xvA.x, xvA.y), wx);
                    wh = fma2(pack2(wgtA, wgtA), pack2(hA0, hA1), wh);
                    wx = fma2(pack2(wgtB, wgtB), pack2(xvB.x, xvB.y), wx);
                    wh = fma2(pack2(wgtB, wgtB), pack2(hB0, hB1), wh);
                    sw += wgtA + wgtB;
                }
            }

            float a, b;
            unpack2(wx, a, b);
            ((float2*)g_acc)[(size_t)i * 64 + lane] = make_float2(a, b);
            unpack2(wh, a, b);
            ((float2*)g_acc)[(size_t)i * 64 + 32 + lane] = make_float2(a, b);
            if (lane == 0) g_den[i] = sw;
        }
    }
}

// ---------------- K_final: tiled GEMM + normalize + skip + block-pooled sums ------
__global__ __launch_bounds__(256) void k_final(const float* __restrict__ We2,
                                               const float* __restrict__ be2,
                                               const int* __restrict__ batch,
                                               float* __restrict__ out) {
    __shared__ __align__(16) unsigned long long ws2[64 * 32];  // 16KB, [h][lane]
    __shared__ __align__(16) float hs[64 * 64];                // 16KB h tile / partials
    __shared__ __align__(16) float hl4s[64];
    __shared__ float wi_s[64], den_s[64];
    __shared__ int gb_s[64];
    __shared__ int s_cnt[8];

    int t = threadIdx.x, lane = t & 31, w = t >> 5;
    int base = blockIdx.x * 64;

#pragma unroll
    for (int j = 0; j < 8; j++) {
        int idx = t + j * 256;
        int h = idx >> 5, l = idx & 31;
        ws2[idx] = pack2(__ldg(&We2[(2 * l) * 64 + h]), __ldg(&We2[(2 * l + 1) * 64 + h]));
    }
    if (t < 64) {
        hl4s[t] = g_hloop[t];
        int i = base + t;
        if (i < N_NODES) {
            float al = g_ax[i] + g_aloop[0];
            al = al > 0.f ? al : 0.2f * al;
            float wi = __expf(al);
            wi_s[t] = wi;
            den_s[t] = g_den[i] + wi;
            gb_s[t] = __ldg(&batch[i]);
        } else {
            wi_s[t] = 0.f; den_s[t] = 1.f; gb_s[t] = -1;
        }
    }
    __syncthreads();

#pragma unroll
    for (int j = 0; j < 4; j++) {
        int idx = t + j * 256;
        int nl = idx >> 4, q = idx & 15;
        int i = base + nl;
        float4 a = make_float4(0.f, 0.f, 0.f, 0.f);
        if (i < N_NODES) a = *(const float4*)&g_acc[(size_t)i * 128 + 64 + q * 4];
        float wi = wi_s[nl];
        float4 hv = *(const float4*)&hl4s[q * 4];
        a.x += wi * hv.x; a.y += wi * hv.y; a.z += wi * hv.z; a.w += wi * hv.w;
        *(float4*)&hs[nl * 64 + q * 4] = a;
    }
    __syncthreads();

    unsigned long long acc[8];
#pragma unroll
    for (int n = 0; n < 8; n++) acc[n] = pack2(0.f, 0.f);
    // quad-k inner loop: 4 weight vectors + float4 h broadcasts
#pragma unroll 4
    for (int k4 = 0; k4 < 16; k4++) {
        unsigned long long wv0 = ws2[(4 * k4 + 0) * 32 + lane];
        unsigned long long wv1 = ws2[(4 * k4 + 1) * 32 + lane];
        unsigned long long wv2 = ws2[(4 * k4 + 2) * 32 + lane];
        unsigned long long wv3 = ws2[(4 * k4 + 3) * 32 + lane];
#pragma unroll
        for (int n = 0; n < 8; n++) {
            float4 hq = *(const float4*)&hs[(w * 8 + n) * 64 + 4 * k4];
            acc[n] = fma2(pack2(hq.x, hq.x), wv0, acc[n]);
            acc[n] = fma2(pack2(hq.y, hq.y), wv1, acc[n]);
            acc[n] = fma2(pack2(hq.z, hq.z), wv2, acc[n]);
            acc[n] = fma2(pack2(hq.w, hq.w), wv3, acc[n]);
        }
    }

    float2 be2v = __ldg((const float2*)be2 + lane);
    float xo0[8], xo1[8];
    int gb[8];
#pragma unroll
    for (int n = 0; n < 8; n++) {
        int nl = w * 8 + n;
        int i = base + nl;
        gb[n] = gb_s[nl];
        if (i < N_NODES) {
            float wi = wi_s[nl], den = den_s[nl];
            float2 ac = *(const float2*)&g_acc[(size_t)i * 128 + 2 * lane];
            float2 xt = *(const float2*)&g_xtrans[(size_t)i * 64 + 2 * lane];
            float2 sk = *(const float2*)&g_skip[(size_t)i * 64 + 2 * lane];
            float o0, o1;
            unpack2(acc[n], o0, o1);
            o0 = ac.x + wi * xt.x + o0 + den * be2v.x;
            o1 = ac.y + wi * xt.y + o1 + den * be2v.y;
            float inv = 1.f / (den + 1e-16f);
            xo0[n] = o0 * inv + sk.x;
            xo1[n] = o1 * inv + sk.y;
            *(float2*)&out[(size_t)i * 64 + 2 * lane] = make_float2(xo0[n], xo1[n]);
        } else {
            xo0[n] = 0.f; xo1[n] = 0.f;
        }
    }
    __syncthreads();  // done with hs tile; reuse as per-warp partials [8][64]

    int lastValid = min(base + 63, N_NODES - 1) - base;
    int g_lo = gb_s[0], g_hi = gb_s[lastValid];
    for (int g = g_lo; g <= g_hi; g++) {
        float p0 = 0.f, p1 = 0.f;
        int c = 0;
#pragma unroll
        for (int n = 0; n < 8; n++) {
            if (gb[n] == g) { p0 += xo0[n]; p1 += xo1[n]; c++; }
        }
        hs[w * 64 + 2 * lane] = p0;
        hs[w * 64 + 2 * lane + 1] = p1;
        if (lane == 0) s_cnt[w] = c;
        __syncthreads();
        if (t < 64) {
            float v = 0.f;
#pragma unroll
            for (int ww = 0; ww < 8; ww++) v += hs[ww * 64 + t];
            atomicAdd(&g_sums[g * 64 + t], v);
        }
        if (t == 64) {
            int v = 0;
#pragma unroll
            for (int ww = 0; ww < 8; ww++) v += s_cnt[ww];
            atomicAdd(&g_cnt[g], (float)v);
        }
        __syncthreads();
    }
}

// ---------------- K_cls ------------------------------------------------------------
__global__ void k_cls(const float* __restrict__ Wc1, const float* __restrict__ bc1,
                      const float* __restrict__ Wc2, const float* __restrict__ bc2,
                      float* __restrict__ out) {
    __shared__ float reps[4096];
    __shared__ float hid[4096];
    int t = threadIdx.x;  // 256
    for (int i = t; i < 4096; i += 256) {
        int g = i >> 6;
        float cnt = fmaxf(g_cnt[g], 1.f);
        float r = g_sums[i] / cnt;
        reps[i] = r;
        out[N_NODES * 64 + i] = r;
    }
    __syncthreads();
    for (int i = t; i < 4096; i += 256) {
        int g = i >> 6, d = i & 63;
        float s = __ldg(&bc1[d]);
        for (int h = 0; h < 64; h++) s += reps[g * 64 + h] * __ldg(&Wc1[d * 64 + h]);
        hid[i] = fmaxf(s, 0.f);
    }
    __syncthreads();
    for (int i = t; i < 640; i += 256) {
        int g = i / 10, o = i % 10;
        float s = __ldg(&bc2[o]);
        for (int h = 0; h < 64; h++) s += hid[g * 64 + h] * __ldg(&Wc2[o * 64 + h]);
        out[N_NODES * 64 + 4096 + i] = s;
    }
}

// ---------------- launch -----------------------------------------------------------
extern "C" void kernel_launch(void* const* d_in, const int* in_sizes, int n_in,
                              void* d_out, int out_size) {
    const float* x     = (const float*)d_in[0];
    const int*   ei    = (const int*)d_in[1];
    const float* ea    = (const float*)d_in[2];
    const int*   batch = (const int*)d_in[3];
    const float* Wlin  = (const float*)d_in[4];
    const float* We1   = (const float*)d_in[5];
    const float* be1   = (const float*)d_in[6];
    const float* We2   = (const float*)d_in[7];
    const float* be2   = (const float*)d_in[8];
    const float* att   = (const float*)d_in[9];
    const float* Wskip = (const float*)d_in[10];
    const float* Wc1   = (const float*)d_in[11];
    const float* bc1   = (const float*)d_in[12];
    const float* Wc2   = (const float*)d_in[13];
    const float* bc2   = (const float*)d_in[14];
    float* out = (float*)d_out;

    kpre<<<104, 256>>>(Wlin, Wskip, We1, be1, We2, be2, att);
    k_nb<<<7813, 256>>>(x, att, ei);
    k_gather<<<444, 256>>>(ei, ea);
    k_final<<<(N_NODES + 63) / 64, 256>>>(We2, be2, batch, out);
    k_cls<<<1, 256>>>(Wc1, bc1, Wc2, bc2, out);
}

// round 17
// speedup vs baseline: 1.0078x; 1.0078x over previous
#include <cuda_runtime.h>
#include <math.h>

#define N_NODES 100000
#define N_EDGES 1600000
#define F_IN    128
#define E_DIM   16
#define HID     64
#define G_NUM   64
#define OUT_DIM 10
#define MAXDEG  64

// ---------------- scratch (device globals; no allocations allowed) ----------------
__device__ __align__(16) float g_xtrans[N_NODES * HID];   // 25.6 MB
__device__ __align__(16) float g_skip[N_NODES * HID];     // 25.6 MB
__device__ float  g_ax[N_NODES];
__device__ __align__(16) float g_acc[N_NODES * 128];      // [wx(64) | wh(64)] per node
__device__ float  g_den[N_NODES];
__device__ int    g_cnt_e[N_NODES];                       // edges per dst
__device__ __align__(16) int g_bucket[(size_t)N_NODES * MAXDEG];  // eid per dst slot (25.6 MB)
__device__ __align__(16) float g_wt[128 * 128];           // [k][c] c<64: W_lin, c>=64: W_skip
__device__ __align__(16) float2 g_we1t2[16 * 32];         // [k][lane] = (W_e1[2l][k], W_e1[2l+1][k])
__device__ __align__(16) float g_u[64];                   // W_e2^T . att
__device__ __align__(16) float g_hloop[64];               // relu(b_e1)
__device__ __align__(16) float g_be1_raw[64];             // raw b_e1
__device__ float  g_cscal[1];                             // b_e2 . att
__device__ float  g_aloop[1];                             // hloop.u + c
__device__ float  g_sums[G_NUM * HID];
__device__ float  g_cnt[G_NUM];
__device__ int    g_work;                                 // work-stealing cursor

// ---------------- f32x2 helpers ----------------------------------------------------
__device__ __forceinline__ unsigned long long pack2(float x, float y) {
    unsigned long long r;
    asm("mov.b64 %0, {%1, %2};" : "=l"(r) : "f"(x), "f"(y));
    return r;
}
__device__ __forceinline__ void unpack2(unsigned long long v, float& x, float& y) {
    asm("mov.b64 {%0, %1}, %2;" : "=f"(x), "=f"(y) : "l"(v));
}
__device__ __forceinline__ unsigned long long fma2(unsigned long long a, unsigned long long b,
                                                   unsigned long long c) {
    unsigned long long d;
    asm("fma.rn.f32x2 %0, %1, %2, %3;" : "=l"(d) : "l"(a), "l"(b), "l"(c));
    return d;
}
__device__ __forceinline__ unsigned long long add2(unsigned long long a, unsigned long long b) {
    unsigned long long d;
    asm("add.rn.f32x2 %0, %1, %2;" : "=l"(d) : "l"(a), "l"(b));
    return d;
}
__device__ __forceinline__ float getc(float4 v, int k) {
    return k == 0 ? v.x : (k == 1 ? v.y : (k == 2 ? v.z : v.w));
}

// ---------------- K_pre: weight prep + ALL zeroing ---------------------------------
__global__ void kpre(const float* __restrict__ Wlin, const float* __restrict__ Wskip,
                     const float* __restrict__ We1,  const float* __restrict__ be1,
                     const float* __restrict__ We2,  const float* __restrict__ be2,
                     const float* __restrict__ att) {
    int b = blockIdx.x, t = threadIdx.x;  // grid 104, 256 threads

    for (int i = b * 256 + t; i < N_NODES; i += 104 * 256) g_cnt_e[i] = 0;

    if (b == 1) {
        for (int i = t; i < G_NUM * HID; i += 256) g_sums[i] = 0.f;
        if (t < G_NUM) g_cnt[t] = 0.f;
        if (t == 0) g_work = 0;
    }
    if (b != 0) return;

    for (int i = t; i < 128 * 128; i += 256) {
        int k = i >> 7, c = i & 127;
        g_wt[i] = (c < 64) ? Wlin[c * 128 + k] : Wskip[(c - 64) * 128 + k];
    }
    for (int i = t; i < 16 * 32; i += 256) {
        int k = i >> 5, l = i & 31;
        g_we1t2[i] = make_float2(We1[(2 * l) * 16 + k], We1[(2 * l + 1) * 16 + k]);
    }
    if (t < 64) {
        float uu = 0.f;
        for (int d = 0; d < 64; d++) uu += We2[d * 64 + t] * att[d];
        g_u[t] = uu;
        g_hloop[t] = fmaxf(be1[t], 0.f);
        g_be1_raw[t] = be1[t];
    }
    __syncthreads();
    if (t == 0) {
        float cc = 0.f;
        for (int d = 0; d < 64; d++) cc += be2[d] * att[d];
        g_cscal[0] = cc;
        float al = cc;
        for (int h = 0; h < 64; h++) al += g_hloop[h] * g_u[h];
        g_aloop[0] = al;
    }
}

// ---------------- K_nb: fused node GEMM + edge bucketing --------------------------
__global__ __launch_bounds__(256) void k_nb(const float* __restrict__ x,
                                            const float* __restrict__ att,
                                            const int* __restrict__ ei) {
    __shared__ __align__(16) float xs[64 * 64];
    __shared__ __align__(16) float wsm[64 * 128];
    int b = blockIdx.x;
    int t = threadIdx.x, lane = t & 31, w = t >> 5;

    if (b % 5 != 0) {
        int bb = b - b / 5 - 1;
        int e = bb * 256 + t;
        if (e < N_EDGES) {
            int dst = __ldg(ei + N_EDGES + e);
            int pos = atomicAdd(&g_cnt_e[dst], 1);
            if (pos < MAXDEG) g_bucket[(size_t)dst * MAXDEG + pos] = e;
        }
        return;
    }

    int nodeBase = (b / 5) * 64;

    unsigned long long acc[8][2];
#pragma unroll
    for (int n = 0; n < 8; n++) { acc[n][0] = pack2(0.f, 0.f); acc[n][1] = pack2(0.f, 0.f); }

    for (int kb = 0; kb < 128; kb += 64) {
#pragma unroll
        for (int j = 0; j < 4; j++) {
            int i4 = t + j * 256;
            int nl = i4 >> 4, kk4 = i4 & 15;
            int node = nodeBase + nl;
            float4 v = make_float4(0.f, 0.f, 0.f, 0.f);
            if (node < N_NODES) v = __ldg((const float4*)x + node * 32 + (kb >> 2) + kk4);
            ((float4*)xs)[nl * 16 + kk4] = v;
        }
#pragma unroll
        for (int j = 0; j < 8; j++) {
            int i4 = t + j * 256;
            ((float4*)wsm)[i4] = ((const float4*)g_wt)[((kb + (i4 >> 5)) << 5) + (i4 & 31)];
        }
        __syncthreads();
#pragma unroll 4
        for (int k4 = 0; k4 < 16; k4++) {
            ulonglong2 wv0 = ((const ulonglong2*)wsm)[(4 * k4 + 0) * 32 + lane];
            ulonglong2 wv1 = ((const ulonglong2*)wsm)[(4 * k4 + 1) * 32 + lane];
            ulonglong2 wv2 = ((const ulonglong2*)wsm)[(4 * k4 + 2) * 32 + lane];
            ulonglong2 wv3 = ((const ulonglong2*)wsm)[(4 * k4 + 3) * 32 + lane];
#pragma unroll
            for (int n = 0; n < 8; n++) {
                float4 xq = ((const float4*)xs)[(w * 8 + n) * 16 + k4];
                acc[n][0] = fma2(pack2(xq.x, xq.x), wv0.x, acc[n][0]);
                acc[n][1] = fma2(pack2(xq.x, xq.x), wv0.y, acc[n][1]);
                acc[n][0] = fma2(pack2(xq.y, xq.y), wv1.x, acc[n][0]);
                acc[n][1] = fma2(pack2(xq.y, xq.y), wv1.y, acc[n][1]);
                acc[n][0] = fma2(pack2(xq.z, xq.z), wv2.x, acc[n][0]);
                acc[n][1] = fma2(pack2(xq.z, xq.z), wv2.y, acc[n][1]);
                acc[n][0] = fma2(pack2(xq.w, xq.w), wv3.x, acc[n][0]);
                acc[n][1] = fma2(pack2(xq.w, xq.w), wv3.y, acc[n][1]);
            }
        }
        __syncthreads();
    }

    float4 av = make_float4(0.f, 0.f, 0.f, 0.f);
    if (lane < 16) av = __ldg((const float4*)att + lane);
#pragma unroll
    for (int n = 0; n < 8; n++) {
        int node = nodeBase + w * 8 + n;
        float o0, o1, o2, o3;
        unpack2(acc[n][0], o0, o1);
        unpack2(acc[n][1], o2, o3);
        float part = o0 * av.x + o1 * av.y + o2 * av.z + o3 * av.w;
#pragma unroll
        for (int off = 16; off; off >>= 1) part += __shfl_xor_sync(0xffffffffu, part, off);
        if (node < N_NODES) {
            float4 v = make_float4(o0, o1, o2, o3);
            if (lane < 16) ((float4*)g_xtrans)[node * 16 + lane] = v;
            else           ((float4*)g_skip)[node * 16 + (lane - 16)] = v;
            if (lane == 0) g_ax[node] = part;
        }
    }
}

// ---------------- K_gather: work-stealing, 2-edge ILP, self-loop folded in --------
__global__ __launch_bounds__(256, 3) void k_gather(const int* __restrict__ ei,
                                                   const float* __restrict__ ea) {
    __shared__ __align__(16) float2 wsh[8 * 32];
    int t = threadIdx.x, lane = t & 31;
    int half = lane >> 4;
#pragma unroll
    for (int j = t; j < 256; j += 256) wsh[j] = g_we1t2[256 + j];
    __syncthreads();

    unsigned long long w2r[8];
#pragma unroll
    for (int k = 0; k < 8; k++) {
        float2 f = g_we1t2[k * 32 + lane];
        w2r[k] = pack2(f.x, f.y);
    }
    float bx = g_be1_raw[2 * lane], by = g_be1_raw[2 * lane + 1];
    float2 uu = ((const float2*)g_u)[lane];
    float cconst = g_cscal[0];

    while (true) {
        int base;
        if (lane == 0) base = atomicAdd(&g_work, 4);
        base = __shfl_sync(0xffffffffu, base, 0);
        if (base >= N_NODES) break;
        int lim = min(base + 4, N_NODES);

        for (int i = base; i < lim; i++) {
            int n = min(g_cnt_e[i], MAXDEG);
            const int* row = g_bucket + (size_t)i * MAXDEG;

            unsigned long long wx = pack2(0.f, 0.f), wh = pack2(0.f, 0.f);
            float sw = 0.f;

            if (n > 0) {
                int m = n - 1;
                int eA = __ldg(row);
                int eB = __ldg(row + min(1, m));
                int sA = __ldg(ei + eA);
                int sB = __ldg(ei + eB);

                for (int j = 0; j < n; j += 2) {
                    bool hasB = (j + 1 < n);
                    int ceA = eA, ceB = eB, csA = sA, csB = sB;

                    eA = __ldg(row + min(j + 2, m));
                    eB = __ldg(row + min(j + 3, m));
                    sA = __ldg(ei + eA);
                    sB = __ldg(ei + eB);

                    float axA = __ldg(&g_ax[csA]);
                    float axB = __ldg(&g_ax[csB]);
                    float2 xvA = __ldg((const float2*)g_xtrans + (size_t)csA * 32 + lane);
                    float2 xvB = __ldg((const float2*)g_xtrans + (size_t)csB * 32 + lane);

                    const float4* qA = (const float4*)ea + (size_t)ceA * 4;
                    const float4* qB = (const float4*)ea + (size_t)ceB * 4;

                    unsigned long long hA = pack2(bx, by), hB = pack2(bx, by);
                    {
                        float4 A0 = __ldg(qA), A1 = __ldg(qA + 1);
                        float4 B0 = __ldg(qB), B1 = __ldg(qB + 1);
#pragma unroll
                        for (int k = 0; k < 4; k++) {
                            float a = getc(A0, k), b = getc(B0, k);
                            hA = fma2(pack2(a, a), w2r[k], hA);
                            hB = fma2(pack2(b, b), w2r[k], hB);
                        }
#pragma unroll
                        for (int k = 0; k < 4; k++) {
                            float a = getc(A1, k), b = getc(B1, k);
                            hA = fma2(pack2(a, a), w2r[4 + k], hA);
                            hB = fma2(pack2(b, b), w2r[4 + k], hB);
                        }
                    }
                    {
                        float4 A0 = __ldg(qA + 2), A1 = __ldg(qA + 3);
                        float4 B0 = __ldg(qB + 2), B1 = __ldg(qB + 3);
#pragma unroll
                        for (int k = 0; k < 4; k++) {
                            float2 wk = wsh[k * 32 + lane];
                            unsigned long long wkp = pack2(wk.x, wk.y);
                            float a = getc(A0, k), b = getc(B0, k);
                            hA = fma2(pack2(a, a), wkp, hA);
                            hB = fma2(pack2(b, b), wkp, hB);
                        }
#pragma unroll
                        for (int k = 0; k < 4; k++) {
                            float2 wk = wsh[(4 + k) * 32 + lane];
                            unsigned long long wkp = pack2(wk.x, wk.y);
                            float a = getc(A1, k), b = getc(B1, k);
                            hA = fma2(pack2(a, a), wkp, hA);
                            hB = fma2(pack2(b, b), wkp, hB);
                        }
                    }

                    float hA0, hA1, hB0, hB1;
                    unpack2(hA, hA0, hA1);
                    unpack2(hB, hB0, hB1);
                    hA0 = fmaxf(hA0, 0.f); hA1 = fmaxf(hA1, 0.f);
                    hB0 = fmaxf(hB0, 0.f); hB1 = fmaxf(hB1, 0.f);

                    float pA = hA0 * uu.x + hA1 * uu.y;
                    float pB = hB0 * uu.x + hB1 * uu.y;
                    float zA = pA + __shfl_xor_sync(0xffffffffu, pA, 16);
                    float zB = pB + __shfl_xor_sync(0xffffffffu, pB, 16);
                    float z = half ? zB : zA;
#pragma unroll
                    for (int off = 8; off; off >>= 1) z += __shfl_xor_sync(0xffffffffu, z, off);

                    float al = (half ? axB : axA) + z + cconst;
                    al = al > 0.f ? al : 0.2f * al;
                    bool valid = (half == 0) || hasB;
                    float wgt = valid ? __expf(al) : 0.f;
                    float wgtO = __shfl_xor_sync(0xffffffffu, wgt, 16);
                    float wgtA = half ? wgtO : wgt;
                    float wgtB = half ? wgt : wgtO;

                    wx = fma2(pack2(wgtA, wgtA), pack2(xvA.x, xvA.y), wx);
                    wh = fma2(pack2(wgtA, wgtA), pack2(hA0, hA1), wh);
                    wx = fma2(pack2(wgtB, wgtB), pack2(xvB.x, xvB.y), wx);
                    wh = fma2(pack2(wgtB, wgtB), pack2(hB0, hB1), wh);
                    sw += wgtA + wgtB;
                }
            }

            // ---- self-loop folded in: wi*xtrans[i], wi*hloop, wi ----
            float ali = __ldg(&g_ax[i]) + g_aloop[0];
            ali = ali > 0.f ? ali : 0.2f * ali;
            float wi = __expf(ali);
            float2 xti = __ldg((const float2*)g_xtrans + (size_t)i * 32 + lane);
            float2 hli = __ldg((const float2*)g_hloop + lane);
            unsigned long long wip = pack2(wi, wi);
            wx = fma2(wip, pack2(xti.x, xti.y), wx);
            wh = fma2(wip, pack2(hli.x, hli.y), wh);
            sw += wi;

            float a, b;
            unpack2(wx, a, b);
            ((float2*)g_acc)[(size_t)i * 64 + lane] = make_float2(a, b);
            unpack2(wh, a, b);
            ((float2*)g_acc)[(size_t)i * 64 + 32 + lane] = make_float2(a, b);
            if (lane == 0) g_den[i] = sw;
        }
    }
}

// ---------------- K_final: GEMV + normalize + skip + block-pooled sums ------------
__global__ __launch_bounds__(256) void k_final(const float* __restrict__ We2,
                                               const float* __restrict__ be2,
                                               const int* __restrict__ batch,
                                               float* __restrict__ out) {
    __shared__ __align__(16) unsigned long long ws2[64 * 32];  // 16KB, [h][lane]
    __shared__ __align__(16) float hs[64 * 64];                // 16KB h tile / partials
    __shared__ float den_s[64];
    __shared__ int gb_s[64];
    __shared__ int s_cnt[8];

    int t = threadIdx.x, lane = t & 31, w = t >> 5;
    int base = blockIdx.x * 64;

#pragma unroll
    for (int j = 0; j < 8; j++) {
        int idx = t + j * 256;
        int h = idx >> 5, l = idx & 31;
        ws2[idx] = pack2(__ldg(&We2[(2 * l) * 64 + h]), __ldg(&We2[(2 * l + 1) * 64 + h]));
    }
    if (t < 64) {
        int i = base + t;
        if (i < N_NODES) {
            den_s[t] = g_den[i];
            gb_s[t] = __ldg(&batch[i]);
        } else {
            den_s[t] = 1.f; gb_s[t] = -1;
        }
    }
    __syncthreads();

#pragma unroll
    for (int j = 0; j < 4; j++) {
        int idx = t + j * 256;
        int nl = idx >> 4, q = idx & 15;
        int i = base + nl;
        float4 a = make_float4(0.f, 0.f, 0.f, 0.f);
        if (i < N_NODES) a = *(const float4*)&g_acc[(size_t)i * 128 + 64 + q * 4];
        *(float4*)&hs[nl * 64 + q * 4] = a;
    }
    __syncthreads();

    unsigned long long acc[8];
#pragma unroll
    for (int n = 0; n < 8; n++) acc[n] = pack2(0.f, 0.f);
#pragma unroll 4
    for (int k4 = 0; k4 < 16; k4++) {
        unsigned long long wv0 = ws2[(4 * k4 + 0) * 32 + lane];
        unsigned long long wv1 = ws2[(4 * k4 + 1) * 32 + lane];
        unsigned long long wv2 = ws2[(4 * k4 + 2) * 32 + lane];
        unsigned long long wv3 = ws2[(4 * k4 + 3) * 32 + lane];
#pragma unroll
        for (int n = 0; n < 8; n++) {
            float4 hq = *(const float4*)&hs[(w * 8 + n) * 64 + 4 * k4];
            acc[n] = fma2(pack2(hq.x, hq.x), wv0, acc[n]);
            acc[n] = fma2(pack2(hq.y, hq.y), wv1, acc[n]);
            acc[n] = fma2(pack2(hq.z, hq.z), wv2, acc[n]);
            acc[n] = fma2(pack2(hq.w, hq.w), wv3, acc[n]);
        }
    }

    float2 be2v = __ldg((const float2*)be2 + lane);
    float xo0[8], xo1[8];
    int gb[8];
#pragma unroll
    for (int n = 0; n < 8; n++) {
        int nl = w * 8 + n;
        int i = base + nl;
        gb[n] = gb_s[nl];
        if (i < N_NODES) {
            float den = den_s[nl];
            float2 ac = *(const float2*)&g_acc[(size_t)i * 128 + 2 * lane];
            float2 sk = *(const float2*)&g_skip[(size_t)i * 64 + 2 * lane];
            float o0, o1;
            unpack2(acc[n], o0, o1);
            o0 = ac.x + o0 + den * be2v.x;
            o1 = ac.y + o1 + den * be2v.y;
            float inv = 1.f / (den + 1e-16f);
            xo0[n] = o0 * inv + sk.x;
            xo1[n] = o1 * inv + sk.y;
            *(float2*)&out[(size_t)i * 64 + 2 * lane] = make_float2(xo0[n], xo1[n]);
        } else {
            xo0[n] = 0.f; xo1[n] = 0.f;
        }
    }
    __syncthreads();  // done with hs tile; reuse as per-warp partials [8][64]

    int lastValid = min(base + 63, N_NODES - 1) - base;
    int g_lo = gb_s[0], g_hi = gb_s[lastValid];
    for (int g = g_lo; g <= g_hi; g++) {
        float p0 = 0.f, p1 = 0.f;
        int c = 0;
#pragma unroll
        for (int n = 0; n < 8; n++) {
            if (gb[n] == g) { p0 += xo0[n]; p1 += xo1[n]; c++; }
        }
        hs[w * 64 + 2 * lane] = p0;
        hs[w * 64 + 2 * lane + 1] = p1;
        if (lane == 0) s_cnt[w] = c;
        __syncthreads();
        if (t < 64) {
            float v = 0.f;
#pragma unroll
            for (int ww = 0; ww < 8; ww++) v += hs[ww * 64 + t];
            atomicAdd(&g_sums[g * 64 + t], v);
        }
        if (t == 64) {
            int v = 0;
#pragma unroll
            for (int ww = 0; ww < 8; ww++) v += s_cnt[ww];
            atomicAdd(&g_cnt[g], (float)v);
        }
        __syncthreads();
    }
}

// ---------------- K_cls: one block per graph --------------------------------------
__global__ __launch_bounds__(64) void k_cls(const float* __restrict__ Wc1,
                                            const float* __restrict__ bc1,
                                            const float* __restrict__ Wc2,
                                            const float* __restrict__ bc2,
                                            float* __restrict__ out) {
    __shared__ float reps[64];
    __shared__ float hid[64];
    int g = blockIdx.x, t = threadIdx.x;  // 64 blocks x 64 threads
    float cnt = fmaxf(g_cnt[g], 1.f);
    float r = g_sums[g * 64 + t] / cnt;
    reps[t] = r;
    out[N_NODES * 64 + g * 64 + t] = r;
    __syncthreads();
    float s = __ldg(&bc1[t]);
#pragma unroll 8
    for (int h = 0; h < 64; h++) s += reps[h] * __ldg(&Wc1[t * 64 + h]);
    hid[t] = fmaxf(s, 0.f);
    __syncthreads();
    if (t < OUT_DIM) {
        float s2 = __ldg(&bc2[t]);
#pragma unroll 8
        for (int h = 0; h < 64; h++) s2 += hid[h] * __ldg(&Wc2[t * 64 + h]);
        out[N_NODES * 64 + 4096 + g * 10 + t] = s2;
    }
}

// ---------------- launch -----------------------------------------------------------
extern "C" void kernel_launch(void* const* d_in, const int* in_sizes, int n_in,
                              void* d_out, int out_size) {
    const float* x     = (const float*)d_in[0];
    const int*   ei    = (const int*)d_in[1];
    const float* ea    = (const float*)d_in[2];
    const int*   batch = (const int*)d_in[3];
    const float* Wlin  = (const float*)d_in[4];
    const float* We1   = (const float*)d_in[5];
    const float* be1   = (const float*)d_in[6];
    const float* We2   = (const float*)d_in[7];
    const float* be2   = (const float*)d_in[8];
    const float* att   = (const float*)d_in[9];
    const float* Wskip = (const float*)d_in[10];
    const float* Wc1   = (const float*)d_in[11];
    const float* bc1   = (const float*)d_in[12];
    const float* Wc2   = (const float*)d_in[13];
    const float* bc2   = (const float*)d_in[14];
    float* out = (float*)d_out;

    kpre<<<104, 256>>>(Wlin, Wskip, We1, be1, We2, be2, att);
    k_nb<<<7813, 256>>>(x, att, ei);
    k_gather<<<444, 256>>>(ei, ea);
    k_final<<<(N_NODES + 63) / 64, 256>>>(We2, be2, batch, out);
    k_cls<<<64, 64>>>(Wc1, bc1, Wc2, bc2, out);
}